// round 4
// baseline (speedup 1.0000x reference)
#include <cuda_runtime.h>

typedef unsigned long long ull;

#define TW 4
#define C_ 64
#define D_ 32
#define S_ 32
#define SP_ 16
#define H_ 64
#define W_ 64
#define B_ 4
#define HW_ 4096
#define DHW_ 131072

#define XROW 68          /* x-tile: [w][d][c-contig], d-row stride */
#define PIXST 2184       /* 32*68 + 8 pad */
#define OROW 35          /* out-tile: [c][w][d] */
#define OFF_R1 0
#define N_R1 8960        /* max(4*2184=8736, 64*4*35=8960) */
#define KT_ROW 36
#define VS_ROW 68
#define N_PW (D_*KT_ROW + SP_*VS_ROW)   /* 2240 */
#define OFF_SC N_R1
#define SMEM_FLOATS (OFF_SC + 4*N_PW)   /* 17920 floats = 71680 B */

__device__ __forceinline__ ull f2fma(ull a, ull b, ull c) {
    ull d; asm("fma.rn.f32x2 %0,%1,%2,%3;" : "=l"(d) : "l"(a), "l"(b), "l"(c)); return d;
}
__device__ __forceinline__ ull f2add(ull a, ull b) {
    ull d; asm("add.rn.f32x2 %0,%1,%2;" : "=l"(d) : "l"(a), "l"(b)); return d;
}
__device__ __forceinline__ ull f2dup(float x) {
    ull d; asm("mov.b64 %0,{%1,%1};" : "=l"(d) : "f"(x)); return d;
}
__device__ __forceinline__ ull f2pack(float x, float y) {
    ull d; asm("mov.b64 %0,{%1,%2};" : "=l"(d) : "f"(x), "f"(y)); return d;
}
__device__ __forceinline__ float2 f2unpack(ull a) {
    float lo, hi; asm("mov.b64 {%0,%1},%2;" : "=f"(lo), "=f"(hi) : "l"(a));
    return make_float2(lo, hi);
}
__device__ __forceinline__ ulonglong2 ldg128(const float* p) {
    return __ldg((const ulonglong2*)p);
}

/* one projection output channel s: dot(W[s,:], x) + b[s], c-pair packed.
   Weights via LDG (L1-resident broadcast), floor 4/SMSP vs LDC's 8. */
#define PROJ_S(WPTR, BPTR, sIdx, val) {                                      \
    ull pa0=0ULL, pa1=0ULL, pa2=0ULL, pa3=0ULL;                              \
    _Pragma("unroll")                                                        \
    for (int t = 0; t < 16; t += 2) {                                        \
        const ulonglong2 wA = ldg128(WPTR + (sIdx)*C_ + 4*t);                \
        pa0 = f2fma(wA.x, x2[2*t],   pa0);                                   \
        pa1 = f2fma(wA.y, x2[2*t+1], pa1);                                   \
        const ulonglong2 wB = ldg128(WPTR + (sIdx)*C_ + 4*t + 4);            \
        pa2 = f2fma(wB.x, x2[2*t+2], pa2);                                   \
        pa3 = f2fma(wB.y, x2[2*t+3], pa3);                                   \
    }                                                                        \
    const float2 pp = f2unpack(f2add(f2add(pa0,pa2), f2add(pa1,pa3)));       \
    val = pp.x + pp.y + __ldg(BPTR + (sIdx));                                \
}

__global__ void __launch_bounds__(128, 3)
attn_fused_kernel(const float* __restrict__ x,
                  const float* __restrict__ Wk, const float* __restrict__ bk,
                  const float* __restrict__ Wq, const float* __restrict__ bq,
                  const float* __restrict__ Wv, const float* __restrict__ bv,
                  const float* __restrict__ Wo, const float* __restrict__ bo,
                  float* __restrict__ out)
{
    extern __shared__ float sm[];
    const int tid = threadIdx.x;
    const int bx  = blockIdx.x;
    const int wt  = bx & 15;
    const int h   = (bx >> 4) & 63;
    const int b   = bx >> 10;
    const int w0  = wt * TW;
    const int xbase = b*C_*DHW_ + h*W_ + w0;

    /* ---- stage x tile: [w][d][c-contig] ---- */
    for (int e = tid; e < C_*D_*TW; e += 128) {
        const int w = e & 3;
        const int d = (e >> 2) & 31;
        const int c = e >> 7;
        sm[OFF_R1 + w*PIXST + d*XROW + c] = x[xbase + c*DHW_ + d*HW_ + w];
    }
    __syncthreads();

    const int warp = tid >> 5;    /* pixel */
    const int lane = tid & 31;    /* d (and j) */

    /* ---- x fully into registers (16 LDS.128, conflict-free) ---- */
    ull x2[32];
    {
        const float* xr = sm + OFF_R1 + warp*PIXST + lane*XROW;
#pragma unroll
        for (int t = 0; t < 16; t++) {
            const ulonglong2 v = *(const ulonglong2*)&xr[4*t];
            x2[2*t] = v.x; x2[2*t+1] = v.y;
        }
    }
    __syncthreads();   /* x-tile region now dead -> reuse as out-tile */

    /* ---- pre-write residual into out-tile [c][w][d] ---- */
    float* otile = sm + OFF_R1;
#pragma unroll
    for (int cp = 0; cp < 32; cp++) {
        const float2 p = f2unpack(x2[cp]);
        otile[((2*cp  )*TW + warp)*OROW + lane] = p.x;
        otile[((2*cp+1)*TW + warp)*OROW + lane] = p.y;
    }

    float* kT = sm + OFF_SC + warp*N_PW;   /* kT[i][s], stride KT_ROW */
    float* vS = kT + D_*KT_ROW;            /* vS[sp][2i], stride VS_ROW */

    /* ---- K pass ---- */
#pragma unroll 4
    for (int sp = 0; sp < SP_; sp++) {
        float v0, v1;
        PROJ_S(Wk, bk, 2*sp,   v0);
        PROJ_S(Wk, bk, 2*sp+1, v1);
        *(ull*)&kT[lane*KT_ROW + 2*sp] = f2pack(v0, v1);
    }

    /* ---- Q pass (kept in registers) ---- */
    ull q2[SP_];
#pragma unroll
    for (int sp = 0; sp < SP_; sp++) {
        float v0, v1;
        PROJ_S(Wq, bq, 2*sp,   v0);
        PROJ_S(Wq, bq, 2*sp+1, v1);
        q2[sp] = f2pack(v0, v1);
    }

    /* ---- V pass ---- */
#pragma unroll 4
    for (int sp = 0; sp < SP_; sp++) {
        float v0, v1;
        PROJ_S(Wv, bv, 2*sp,   v0);
        PROJ_S(Wv, bv, 2*sp+1, v1);
        *(ull*)&vS[sp*VS_ROW + 2*lane] = f2pack(v0, v1);
    }
    __syncwarp();

    /* ---- scores[i][j=lane] ---- */
    float a[D_];
#pragma unroll
    for (int i = 0; i < D_; i++) {
        ull a0 = 0ULL, a1 = 0ULL;
#pragma unroll
        for (int t = 0; t < 8; t++) {
            const ulonglong2 kk = *(const ulonglong2*)&kT[i*KT_ROW + 4*t];
            a0 = f2fma(kk.x, q2[2*t],   a0);
            a1 = f2fma(kk.y, q2[2*t+1], a1);
        }
        const float2 p = f2unpack(f2add(a0, a1));
        a[i] = (p.x + p.y) * 0.17677669529663687f;
    }

    /* ---- softmax over i ---- */
    float m = a[0];
#pragma unroll
    for (int i = 1; i < D_; i++) m = fmaxf(m, a[i]);
    float ssum = 0.f;
#pragma unroll
    for (int i = 0; i < D_; i++) { a[i] = __expf(a[i] - m); ssum += a[i]; }
    const float inv = 1.0f / ssum;

    ull ad[D_];
#pragma unroll
    for (int i = 0; i < D_; i++) ad[i] = f2dup(a[i] * inv);

    /* ---- o[sp][j=lane] = sum_i v[s][i] a[i] ---- */
    ull o2[SP_];
#pragma unroll
    for (int sp = 0; sp < SP_; sp++) {
        ull a0 = 0ULL, a1 = 0ULL;
#pragma unroll
        for (int t = 0; t < 16; t++) {
            const ulonglong2 vv = *(const ulonglong2*)&vS[sp*VS_ROW + 4*t];
            a0 = f2fma(vv.x, ad[2*t],   a0);
            a1 = f2fma(vv.y, ad[2*t+1], a1);
        }
        o2[sp] = f2add(a0, a1);
    }

    /* ---- out[c] += Wo[c,:]·o + bo ---- */
#pragma unroll 8
    for (int c = 0; c < C_; c++) {
        ull a0 = 0ULL, a1 = 0ULL;
#pragma unroll
        for (int t = 0; t < 8; t++) {
            const ulonglong2 ww = ldg128(Wo + c*S_ + 4*t);
            a0 = f2fma(ww.x, o2[2*t],   a0);
            a1 = f2fma(ww.y, o2[2*t+1], a1);
        }
        const float2 p = f2unpack(f2add(a0, a1));
        otile[(c*TW + warp)*OROW + lane] += p.x + p.y + __ldg(bo + c);
    }
    __syncthreads();

    /* ---- coalesced store ---- */
    for (int e = tid; e < C_*D_*TW; e += 128) {
        const int w = e & 3;
        const int d = (e >> 2) & 31;
        const int c = e >> 7;
        out[xbase + c*DHW_ + d*HW_ + w] = sm[OFF_R1 + (c*TW + w)*OROW + d];
    }
}

extern "C" void kernel_launch(void* const* d_in, const int* in_sizes, int n_in,
                              void* d_out, int out_size)
{
    const float* x  = (const float*)d_in[0];
    const float* Wk = (const float*)d_in[1];
    const float* bk = (const float*)d_in[2];
    const float* Wq = (const float*)d_in[3];
    const float* bq = (const float*)d_in[4];
    const float* Wv = (const float*)d_in[5];
    const float* bv = (const float*)d_in[6];
    const float* Wo = (const float*)d_in[7];
    const float* bo = (const float*)d_in[8];
    float* out = (float*)d_out;

    const size_t smem_bytes = (size_t)SMEM_FLOATS * sizeof(float);
    cudaFuncSetAttribute(attn_fused_kernel,
                         cudaFuncAttributeMaxDynamicSharedMemorySize,
                         (int)smem_bytes);

    const int grid = B_ * H_ * (W_ / TW);   /* 4096 blocks */
    attn_fused_kernel<<<grid, 128, smem_bytes>>>(x, Wk, bk, Wq, bq, Wv, bv, Wo, bo, out);
}

// round 5
// speedup vs baseline: 2.0429x; 2.0429x over previous
#include <cuda_runtime.h>

typedef unsigned long long ull;

#define TW 4
#define C_ 64
#define D_ 32
#define S_ 32
#define SP_ 16
#define H_ 64
#define W_ 64
#define B_ 4
#define HW_ 4096
#define DHW_ 131072

#define XROW 68          /* x-tile: [w][d][c-contig], d-row stride */
#define PIXST 2184       /* 32*68 + 8 pad */
#define OROW 35          /* out-tile: [c][w][d] */
#define OFF_R1 0
#define N_R1 8960        /* max(4*2184=8736, 64*4*35=8960) */
/* weights in smem */
#define OFF_WK (OFF_R1 + N_R1)          /* [s][c] native */
#define OFF_WQ (OFF_WK + S_*C_)
#define OFF_WV (OFF_WQ + S_*C_)
#define OFF_WO (OFF_WV + S_*C_)         /* [c][s] native */
#define OFF_BK (OFF_WO + C_*S_)
#define OFF_BQ (OFF_BK + S_)
#define OFF_BV (OFF_BQ + S_)
#define OFF_BO (OFF_BV + S_)
#define KT_ROW 36
#define VS_ROW 68
#define N_PW (D_*KT_ROW + SP_*VS_ROW)   /* 2240 */
#define OFF_SC (OFF_BO + C_)            /* 17312 */
#define SMEM_FLOATS (OFF_SC + 4*N_PW)   /* 26272 floats = 105088 B */

__device__ __forceinline__ ull f2fma(ull a, ull b, ull c) {
    ull d; asm("fma.rn.f32x2 %0,%1,%2,%3;" : "=l"(d) : "l"(a), "l"(b), "l"(c)); return d;
}
__device__ __forceinline__ ull f2add(ull a, ull b) {
    ull d; asm("add.rn.f32x2 %0,%1,%2;" : "=l"(d) : "l"(a), "l"(b)); return d;
}
__device__ __forceinline__ ull f2dup(float x) {
    ull d; asm("mov.b64 %0,{%1,%1};" : "=l"(d) : "f"(x)); return d;
}
__device__ __forceinline__ ull f2pack(float x, float y) {
    ull d; asm("mov.b64 %0,{%1,%2};" : "=l"(d) : "f"(x), "f"(y)); return d;
}
__device__ __forceinline__ float2 f2unpack(ull a) {
    float lo, hi; asm("mov.b64 {%0,%1},%2;" : "=f"(lo), "=f"(hi) : "l"(a));
    return make_float2(lo, hi);
}

/* one projection channel s: dot(W[s,:], x) + b[s]; weights via smem broadcast LDS.128 */
#define PROJ_S(WOFF, BOFF, sIdx, val) {                                      \
    ull pa0=0ULL, pa1=0ULL, pa2=0ULL, pa3=0ULL;                              \
    _Pragma("unroll")                                                        \
    for (int t = 0; t < 16; t += 2) {                                        \
        const ulonglong2 wA = *(const ulonglong2*)&sm[(WOFF) + (sIdx)*C_ + 4*t];     \
        pa0 = f2fma(wA.x, x2[2*t],   pa0);                                   \
        pa1 = f2fma(wA.y, x2[2*t+1], pa1);                                   \
        const ulonglong2 wB = *(const ulonglong2*)&sm[(WOFF) + (sIdx)*C_ + 4*t + 4]; \
        pa2 = f2fma(wB.x, x2[2*t+2], pa2);                                   \
        pa3 = f2fma(wB.y, x2[2*t+3], pa3);                                   \
    }                                                                        \
    const float2 pp = f2unpack(f2add(f2add(pa0,pa2), f2add(pa1,pa3)));       \
    val = pp.x + pp.y + sm[(BOFF) + (sIdx)];                                 \
}

__global__ void __launch_bounds__(128, 2)
attn_fused_kernel(const float* __restrict__ x,
                  const float* __restrict__ Wk, const float* __restrict__ bk,
                  const float* __restrict__ Wq, const float* __restrict__ bq,
                  const float* __restrict__ Wv, const float* __restrict__ bv,
                  const float* __restrict__ Wo, const float* __restrict__ bo,
                  float* __restrict__ out)
{
    extern __shared__ float sm[];
    const int tid = threadIdx.x;
    const int bx  = blockIdx.x;
    const int wt  = bx & 15;
    const int h   = (bx >> 4) & 63;
    const int b   = bx >> 10;
    const int w0  = wt * TW;
    const int xbase = b*C_*DHW_ + h*W_ + w0;

    /* ---- stage weights (native layouts) + biases ---- */
    for (int i = tid; i < S_*C_; i += 128) {
        sm[OFF_WK + i] = Wk[i];
        sm[OFF_WQ + i] = Wq[i];
        sm[OFF_WV + i] = Wv[i];
        sm[OFF_WO + i] = Wo[i];
    }
    if (tid < S_) {
        sm[OFF_BK + tid] = bk[tid];
        sm[OFF_BQ + tid] = bq[tid];
        sm[OFF_BV + tid] = bv[tid];
    }
    if (tid < C_) sm[OFF_BO + tid] = bo[tid];

    /* ---- stage x tile: [w][d][c-contig] ---- */
    for (int e = tid; e < C_*D_*TW; e += 128) {
        const int w = e & 3;
        const int d = (e >> 2) & 31;
        const int c = e >> 7;
        sm[OFF_R1 + w*PIXST + d*XROW + c] = x[xbase + c*DHW_ + d*HW_ + w];
    }
    __syncthreads();

    const int warp = tid >> 5;    /* pixel */
    const int lane = tid & 31;    /* d (and j) */

    /* ---- x fully into registers (16 LDS.128, conflict-free) ---- */
    ull x2[32];
    {
        const float* xr = sm + OFF_R1 + warp*PIXST + lane*XROW;
#pragma unroll
        for (int t = 0; t < 16; t++) {
            const ulonglong2 v = *(const ulonglong2*)&xr[4*t];
            x2[2*t] = v.x; x2[2*t+1] = v.y;
        }
    }
    __syncthreads();   /* x-tile region now dead -> reuse as out-tile */

    /* ---- pre-write residual into out-tile [c][w][d] ---- */
    float* otile = sm + OFF_R1;
#pragma unroll
    for (int cp = 0; cp < 32; cp++) {
        const float2 p = f2unpack(x2[cp]);
        otile[((2*cp  )*TW + warp)*OROW + lane] = p.x;
        otile[((2*cp+1)*TW + warp)*OROW + lane] = p.y;
    }

    float* kT = sm + OFF_SC + warp*N_PW;   /* kT[i][s], stride KT_ROW */
    float* vS = kT + D_*KT_ROW;            /* vS[sp][2i], stride VS_ROW */

    /* ---- K pass ---- */
#pragma unroll 4
    for (int sp = 0; sp < SP_; sp++) {
        float v0, v1;
        PROJ_S(OFF_WK, OFF_BK, 2*sp,   v0);
        PROJ_S(OFF_WK, OFF_BK, 2*sp+1, v1);
        *(ull*)&kT[lane*KT_ROW + 2*sp] = f2pack(v0, v1);
    }

    /* ---- Q pass (kept in registers) ---- */
    ull q2[SP_];
#pragma unroll
    for (int sp = 0; sp < SP_; sp++) {
        float v0, v1;
        PROJ_S(OFF_WQ, OFF_BQ, 2*sp,   v0);
        PROJ_S(OFF_WQ, OFF_BQ, 2*sp+1, v1);
        q2[sp] = f2pack(v0, v1);
    }

    /* ---- V pass ---- */
#pragma unroll 4
    for (int sp = 0; sp < SP_; sp++) {
        float v0, v1;
        PROJ_S(OFF_WV, OFF_BV, 2*sp,   v0);
        PROJ_S(OFF_WV, OFF_BV, 2*sp+1, v1);
        *(ull*)&vS[sp*VS_ROW + 2*lane] = f2pack(v0, v1);
    }
    __syncwarp();

    /* ---- scores[i][j=lane] ---- */
    float a[D_];
#pragma unroll
    for (int i = 0; i < D_; i++) {
        ull a0 = 0ULL, a1 = 0ULL;
#pragma unroll
        for (int t = 0; t < 8; t++) {
            const ulonglong2 kk = *(const ulonglong2*)&kT[i*KT_ROW + 4*t];
            a0 = f2fma(kk.x, q2[2*t],   a0);
            a1 = f2fma(kk.y, q2[2*t+1], a1);
        }
        const float2 p = f2unpack(f2add(a0, a1));
        a[i] = (p.x + p.y) * 0.17677669529663687f;
    }

    /* ---- softmax over i ---- */
    float m = a[0];
#pragma unroll
    for (int i = 1; i < D_; i++) m = fmaxf(m, a[i]);
    float ssum = 0.f;
#pragma unroll
    for (int i = 0; i < D_; i++) { a[i] = __expf(a[i] - m); ssum += a[i]; }
    const float inv = 1.0f / ssum;

    ull ad[D_];
#pragma unroll
    for (int i = 0; i < D_; i++) ad[i] = f2dup(a[i] * inv);

    /* ---- o[sp][j=lane] = sum_i v[s][i] a[i] ---- */
    ull o2[SP_];
#pragma unroll
    for (int sp = 0; sp < SP_; sp++) {
        ull a0 = 0ULL, a1 = 0ULL;
#pragma unroll
        for (int t = 0; t < 16; t++) {
            const ulonglong2 vv = *(const ulonglong2*)&vS[sp*VS_ROW + 4*t];
            a0 = f2fma(vv.x, ad[2*t],   a0);
            a1 = f2fma(vv.y, ad[2*t+1], a1);
        }
        o2[sp] = f2add(a0, a1);
    }

    /* ---- out[c] += Wo[c,:]·o + bo ---- */
#pragma unroll 8
    for (int c = 0; c < C_; c++) {
        ull a0 = 0ULL, a1 = 0ULL;
#pragma unroll
        for (int t = 0; t < 8; t++) {
            const ulonglong2 ww = *(const ulonglong2*)&sm[OFF_WO + c*S_ + 4*t];
            a0 = f2fma(ww.x, o2[2*t],   a0);
            a1 = f2fma(ww.y, o2[2*t+1], a1);
        }
        const float2 p = f2unpack(f2add(a0, a1));
        otile[(c*TW + warp)*OROW + lane] += p.x + p.y + sm[OFF_BO + c];
    }
    __syncthreads();

    /* ---- coalesced store ---- */
    for (int e = tid; e < C_*D_*TW; e += 128) {
        const int w = e & 3;
        const int d = (e >> 2) & 31;
        const int c = e >> 7;
        out[xbase + c*DHW_ + d*HW_ + w] = sm[OFF_R1 + (c*TW + w)*OROW + d];
    }
}

extern "C" void kernel_launch(void* const* d_in, const int* in_sizes, int n_in,
                              void* d_out, int out_size)
{
    const float* x  = (const float*)d_in[0];
    const float* Wk = (const float*)d_in[1];
    const float* bk = (const float*)d_in[2];
    const float* Wq = (const float*)d_in[3];
    const float* bq = (const float*)d_in[4];
    const float* Wv = (const float*)d_in[5];
    const float* bv = (const float*)d_in[6];
    const float* Wo = (const float*)d_in[7];
    const float* bo = (const float*)d_in[8];
    float* out = (float*)d_out;

    const size_t smem_bytes = (size_t)SMEM_FLOATS * sizeof(float);
    cudaFuncSetAttribute(attn_fused_kernel,
                         cudaFuncAttributeMaxDynamicSharedMemorySize,
                         (int)smem_bytes);

    const int grid = B_ * H_ * (W_ / TW);   /* 4096 blocks */
    attn_fused_kernel<<<grid, 128, smem_bytes>>>(x, Wk, bk, Wq, bq, Wv, bv, Wo, bo, out);
}

// round 7
// speedup vs baseline: 2.2528x; 1.1028x over previous
#include <cuda_runtime.h>

typedef unsigned long long ull;

#define TW 4             /* pixels per block (2 warps x 2 pixels/thread) */
#define C_ 64
#define D_ 32
#define S_ 32
#define HW_ 4096
#define DHW_ 131072

#define RX 262           /* x-tile row stride (floats): [d][c*4+w] */
#define OFF_XT 0
#define N_XT (D_*RX)                    /* 8384 */
#define OFF_WTK (OFF_XT + N_XT)         /* WkT [c][s] stride 36 */
#define OFF_WTQ (OFF_WTK + C_*36)
#define OFF_WTV (OFF_WTQ + C_*36)
#define OFF_SC  (OFF_WTV + C_*36)       /* 15296 */
#define SCW 4356                        /* per-warp scratch stride (floats) */
/* per-warp scratch: kT [i=32] rows of 68 floats = 2176, then vS [s=32] rows
   of 68 = 2176. After vS dies, region reused as otile [c=64] rows of 66. */
#define KT_ROWF 68
#define VS_BASE (D_*KT_ROWF)            /* 2176 floats into warp scratch */
#define VS_ROWF 68
#define OT_ROWF 66
#define SMEM_FLOATS (OFF_SC + 2*SCW)    /* 24008 floats = 96032 B */

__constant__ float cWO[C_*S_];
__constant__ float cBK[S_];
__constant__ float cBQ[S_];
__constant__ float cBV[S_];
__constant__ float cBO[C_];

__device__ __forceinline__ ull f2fma(ull a, ull b, ull c) {
    ull d; asm("fma.rn.f32x2 %0,%1,%2,%3;" : "=l"(d) : "l"(a), "l"(b), "l"(c)); return d;
}
__device__ __forceinline__ ull f2add(ull a, ull b) {
    ull d; asm("add.rn.f32x2 %0,%1,%2;" : "=l"(d) : "l"(a), "l"(b)); return d;
}
__device__ __forceinline__ ull f2mul(ull a, ull b) {
    ull d; asm("mul.rn.f32x2 %0,%1,%2;" : "=l"(d) : "l"(a), "l"(b)); return d;
}
__device__ __forceinline__ ull f2dup(float x) {
    ull d; asm("mov.b64 %0,{%1,%1};" : "=l"(d) : "f"(x)); return d;
}
__device__ __forceinline__ ull f2pack(float x, float y) {
    ull d; asm("mov.b64 %0,{%1,%2};" : "=l"(d) : "f"(x), "f"(y)); return d;
}
__device__ __forceinline__ float2 f2unpack(ull a) {
    float lo, hi; asm("mov.b64 {%0,%1},%2;" : "=f"(lo), "=f"(hi) : "l"(a));
    return make_float2(lo, hi);
}

/* one projection pass: accumulate 32 channels for 2 pixels, s-pair accums per pixel. */
#define PROJ_PASS(WOFF, accA, accB) {                                        \
    _Pragma("unroll 4")                                                      \
    for (int c = 0; c < C_; c++) {                                           \
        const ull xp = *(const ull*)&sm[OFF_XT + c*4 + xoff];                \
        const float2 xx = f2unpack(xp);                                      \
        const ull xad = f2dup(xx.x);                                         \
        const ull xbd = f2dup(xx.y);                                         \
        _Pragma("unroll")                                                    \
        for (int g = 0; g < 8; g++) {                                        \
            const ulonglong2 w2 = *(const ulonglong2*)&sm[(WOFF) + c*36 + 4*g]; \
            accA[2*g]   = f2fma(w2.x, xad, accA[2*g]);                       \
            accA[2*g+1] = f2fma(w2.y, xad, accA[2*g+1]);                     \
            accB[2*g]   = f2fma(w2.x, xbd, accB[2*g]);                       \
            accB[2*g+1] = f2fma(w2.y, xbd, accB[2*g+1]);                     \
        }                                                                    \
    }                                                                        \
}

__global__ void __launch_bounds__(64, 2)
attn_fused_kernel(const float* __restrict__ x,
                  const float* __restrict__ Wk,
                  const float* __restrict__ Wq,
                  const float* __restrict__ Wv,
                  float* __restrict__ out)
{
    extern __shared__ float sm[];
    const int tid = threadIdx.x;
    const int bx  = blockIdx.x;
    const int wt  = bx & 15;
    const int h   = (bx >> 4) & 63;
    const int b   = bx >> 10;
    const int w0  = wt * TW;
    const int xbase = b*C_*DHW_ + h*64 + w0;

    /* ---- stage x tile [d][c*4+w] via float4 ---- */
    for (int e = tid; e < C_*D_; e += 64) {
        const int d = e & 31;
        const int c = e >> 5;
        const float4 v4 = *(const float4*)&x[xbase + c*DHW_ + d*HW_];
        *(ull*)&sm[OFF_XT + d*RX + c*4]     = *(const ull*)&v4.x;
        *(ull*)&sm[OFF_XT + d*RX + c*4 + 2] = *(const ull*)&v4.z;
    }
    /* ---- transpose k/q/v weights into smem [c][s] stride 36 ---- */
    for (int i = tid; i < S_*C_; i += 64) {
        const int c = i & 63;
        const int s = i >> 6;
        sm[OFF_WTK + c*36 + s] = Wk[i];
        sm[OFF_WTQ + c*36 + s] = Wq[i];
        sm[OFF_WTV + c*36 + s] = Wv[i];
    }
    __syncthreads();

    const int warp = tid >> 5;        /* pixel pair (2*warp, 2*warp+1) */
    const int lane = tid & 31;        /* d (and j) */
    const int xoff = lane*RX + 2*warp;
    float* sc = sm + OFF_SC + warp*SCW;

    /* ================= K pass ================= */
    {
        ull kA[16], kB[16];
#pragma unroll
        for (int sp = 0; sp < 16; sp++) {
            const ull bb = *(const ull*)&cBK[2*sp];
            kA[sp] = bb; kB[sp] = bb;
        }
        PROJ_PASS(OFF_WTK, kA, kB);
#pragma unroll
        for (int sp = 0; sp < 16; sp++) {
            const float2 a2 = f2unpack(kA[sp]);
            const float2 b2 = f2unpack(kB[sp]);
            ulonglong2 pr;
            pr.x = f2pack(a2.x, b2.x);
            pr.y = f2pack(a2.y, b2.y);
            *(ulonglong2*)&sc[lane*KT_ROWF + 4*sp] = pr;
        }
    }

    /* ================= V pass ================= */
    {
        ull vA[16], vB[16];
#pragma unroll
        for (int sp = 0; sp < 16; sp++) {
            const ull bb = *(const ull*)&cBV[2*sp];
            vA[sp] = bb; vB[sp] = bb;
        }
        PROJ_PASS(OFF_WTV, vA, vB);
#pragma unroll
        for (int sp = 0; sp < 16; sp++) {
            const float2 a2 = f2unpack(vA[sp]);
            const float2 b2 = f2unpack(vB[sp]);
            *(ull*)&sc[VS_BASE + (2*sp  )*VS_ROWF + 2*lane] = f2pack(a2.x, b2.x);
            *(ull*)&sc[VS_BASE + (2*sp+1)*VS_ROWF + 2*lane] = f2pack(a2.y, b2.y);
        }
    }

    /* ================= Q pass (kept in regs, pixel-packed per s) ======= */
    ull q2[32];
    {
        ull qA[16], qB[16];
#pragma unroll
        for (int sp = 0; sp < 16; sp++) {
            const ull bb = *(const ull*)&cBQ[2*sp];
            qA[sp] = bb; qB[sp] = bb;
        }
        PROJ_PASS(OFF_WTQ, qA, qB);
#pragma unroll
        for (int sp = 0; sp < 16; sp++) {
            const float2 a2 = f2unpack(qA[sp]);
            const float2 b2 = f2unpack(qB[sp]);
            q2[2*sp]   = f2pack(a2.x, b2.x);
            q2[2*sp+1] = f2pack(a2.y, b2.y);
        }
    }
    __syncwarp();

    /* ======= scores: app[i] packed over pixels; this lane = column j ======= */
    ull app[32];
#pragma unroll
    for (int i = 0; i < D_; i++) {
        ull a0 = 0ULL, a1 = 0ULL;
#pragma unroll
        for (int g = 0; g < 16; g++) {
            const ulonglong2 kk = *(const ulonglong2*)&sc[i*KT_ROWF + 4*g];
            a0 = f2fma(kk.x, q2[2*g],   a0);
            a1 = f2fma(kk.y, q2[2*g+1], a1);
        }
        app[i] = f2add(a0, a1);
    }

    /* ======= softmax over i, per pixel (scale, max, exp, normalize) ======= */
    {
        const ull scl = f2dup(0.17677669529663687f);  /* 1/sqrt(32) */
        float mA = -1e30f, mB = -1e30f;
#pragma unroll
        for (int i = 0; i < D_; i++) {
            app[i] = f2mul(app[i], scl);
            const float2 p = f2unpack(app[i]);
            mA = fmaxf(mA, p.x); mB = fmaxf(mB, p.y);
        }
        float sA = 0.f, sB = 0.f;
#pragma unroll
        for (int i = 0; i < D_; i++) {
            const float2 p = f2unpack(app[i]);
            const float eA = __expf(p.x - mA);
            const float eB = __expf(p.y - mB);
            app[i] = f2pack(eA, eB);
            sA += eA; sB += eB;
        }
        const ull inv = f2pack(1.0f/sA, 1.0f/sB);
#pragma unroll
        for (int i = 0; i < D_; i++) app[i] = f2mul(app[i], inv);
    }

    /* ======= o[s] packed over pixels ======= */
    ull oA[16], oB[16];
    {
        ull opp[32];
#pragma unroll
        for (int s = 0; s < S_; s++) {
            ull a0 = 0ULL, a1 = 0ULL;
#pragma unroll
            for (int g = 0; g < 16; g++) {
                const ulonglong2 vv = *(const ulonglong2*)&sc[VS_BASE + s*VS_ROWF + 4*g];
                a0 = f2fma(vv.x, app[2*g],   a0);
                a1 = f2fma(vv.y, app[2*g+1], a1);
            }
            opp[s] = f2add(a0, a1);
        }
#pragma unroll
        for (int sp = 0; sp < 16; sp++) {
            const float2 p0 = f2unpack(opp[2*sp]);
            const float2 p1 = f2unpack(opp[2*sp+1]);
            oA[sp] = f2pack(p0.x, p1.x);
            oB[sp] = f2pack(p0.y, p1.y);
        }
    }
    __syncwarp();   /* vS reads done; scratch region reused as otile */

    /* ======= outproj: otile[c][2*lane..] = packed (pixA, pixB) ======= */
#pragma unroll 4
    for (int c = 0; c < C_; c++) {
        ull aA0 = 0ULL, aA1 = 0ULL, aB0 = 0ULL, aB1 = 0ULL;
#pragma unroll
        for (int g = 0; g < 8; g++) {
            const ulonglong2 ww = *(const ulonglong2*)&cWO[c*S_ + 4*g];
            aA0 = f2fma(ww.x, oA[2*g],   aA0);
            aA1 = f2fma(ww.y, oA[2*g+1], aA1);
            aB0 = f2fma(ww.x, oB[2*g],   aB0);
            aB1 = f2fma(ww.y, oB[2*g+1], aB1);
        }
        const float2 pA = f2unpack(f2add(aA0, aA1));
        const float2 pB = f2unpack(f2add(aB0, aB1));
        const float bo = cBO[c];
        *(ull*)&sc[c*OT_ROWF + 2*lane] = f2pack(pA.x + pA.y + bo, pB.x + pB.y + bo);
    }
    __syncthreads();

    /* ======= final: out = otile + residual(x-tile) ======= */
    for (int e = tid; e < C_*D_*TW; e += 64) {
        const int w = e & 3;
        const int d = (e >> 2) & 31;
        const int c = e >> 7;
        const float proj = sm[OFF_SC + (w>>1)*SCW + c*OT_ROWF + 2*d + (w&1)];
        const float res  = sm[OFF_XT + d*RX + c*4 + w];
        out[xbase + c*DHW_ + d*HW_ + w] = proj + res;
    }
}

extern "C" void kernel_launch(void* const* d_in, const int* in_sizes, int n_in,
                              void* d_out, int out_size)
{
    const float* x  = (const float*)d_in[0];
    const float* Wk = (const float*)d_in[1];
    const float* Wq = (const float*)d_in[3];
    const float* Wv = (const float*)d_in[5];
    float* out = (float*)d_out;

    cudaMemcpyToSymbolAsync(cBK, d_in[2], S_*sizeof(float),    0, cudaMemcpyDeviceToDevice, 0);
    cudaMemcpyToSymbolAsync(cBQ, d_in[4], S_*sizeof(float),    0, cudaMemcpyDeviceToDevice, 0);
    cudaMemcpyToSymbolAsync(cBV, d_in[6], S_*sizeof(float),    0, cudaMemcpyDeviceToDevice, 0);
    cudaMemcpyToSymbolAsync(cWO, d_in[7], C_*S_*sizeof(float), 0, cudaMemcpyDeviceToDevice, 0);
    cudaMemcpyToSymbolAsync(cBO, d_in[8], C_*sizeof(float),    0, cudaMemcpyDeviceToDevice, 0);

    const size_t smem_bytes = (size_t)SMEM_FLOATS * sizeof(float);
    cudaFuncSetAttribute(attn_fused_kernel,
                         cudaFuncAttributeMaxDynamicSharedMemorySize,
                         (int)smem_bytes);

    const int grid = 4 * 64 * 16;   /* B * H * (W/TW) = 4096 */
    attn_fused_kernel<<<grid, 64, smem_bytes>>>(x, Wk, Wq, Wv, out);
}